// round 6
// baseline (speedup 1.0000x reference)
#include <cuda_runtime.h>
#include <cstdint>

// ============================================================================
// Problem constants
// ============================================================================
#define K_DIM 12288
#define M_DIM 8192
#define C_DIM 1000
#define N_PAD 1024

// GEMM tiling (int8 TN: A[M,K] row-major, B[N,K] row-major = "col" operand)
#define BM 128
#define BN 128
#define BK 128                      // bytes of K per stage
#define NCHUNK (K_DIM / BK)         // 96
#define STAGES 3
#define A_ST (BM * BK)              // 16384 B
#define B_ST (BN * BK)              // 16384 B
#define STG_BYTES (A_ST + B_ST)     // 32768 B
#define SMEM_BYTES (STAGES * STG_BYTES)  // 98304 B

// ============================================================================
// Device scratch (allocation-free: __device__ globals)
// ============================================================================
__device__ int8_t g_A8[(size_t)M_DIM * K_DIM];   // sign(input)  as s8
__device__ int8_t g_W8[(size_t)N_PAD * K_DIM];   // sign(weight) as s8, zero-pad

// ============================================================================
// Helpers
// ============================================================================
// SW128-style swizzle: 128B rows, XOR 16B-column index with (row % 8)
__device__ __forceinline__ uint32_t swz(uint32_t row, uint32_t col) {
    return row * BK + (col ^ ((row & 7u) * 16u));
}

__device__ __forceinline__ void cp16(uint32_t dst, const void* src) {
    asm volatile("cp.async.cg.shared.global [%0], [%1], 16;"
                 :: "r"(dst), "l"(src));
}
__device__ __forceinline__ void cp_commit() {
    asm volatile("cp.async.commit_group;");
}
__device__ __forceinline__ void cp_wait2() {
    asm volatile("cp.async.wait_group 2;");
}

__device__ __forceinline__ void ldsm_x4(uint32_t& r0, uint32_t& r1,
                                        uint32_t& r2, uint32_t& r3,
                                        uint32_t addr) {
    asm volatile("ldmatrix.sync.aligned.m8n8.x4.shared.b16 {%0,%1,%2,%3}, [%4];"
                 : "=r"(r0), "=r"(r1), "=r"(r2), "=r"(r3) : "r"(addr));
}

__device__ __forceinline__ void imma16832(int* c, const uint32_t* a,
                                          uint32_t b0, uint32_t b1) {
    asm volatile(
        "mma.sync.aligned.m16n8k32.row.col.s32.s8.s8.s32 "
        "{%0,%1,%2,%3}, {%4,%5,%6,%7}, {%8,%9}, {%0,%1,%2,%3};"
        : "+r"(c[0]), "+r"(c[1]), "+r"(c[2]), "+r"(c[3])
        : "r"(a[0]), "r"(a[1]), "r"(a[2]), "r"(a[3]), "r"(b0), "r"(b1));
}

__device__ __forceinline__ int8_t sgn8(float x) {
    return (int8_t)((x > 0.f) - (x < 0.f));
}
__device__ __forceinline__ uint32_t pack4(float4 f) {
    uint32_t a = (uint8_t)sgn8(f.x), b = (uint8_t)sgn8(f.y);
    uint32_t c = (uint8_t)sgn8(f.z), d = (uint8_t)sgn8(f.w);
    return a | (b << 8) | (c << 16) | (d << 24);
}

// ============================================================================
// Kernel 1/2: sign-quantize fp32 -> s8 (16 elems/thread)
// ============================================================================
__global__ void conv_a_kernel(const float4* __restrict__ in) {
    size_t t = (size_t)blockIdx.x * blockDim.x + threadIdx.x;
    const float4* p = in + t * 4;
    uint4 o;
    o.x = pack4(p[0]); o.y = pack4(p[1]); o.z = pack4(p[2]); o.w = pack4(p[3]);
    reinterpret_cast<uint4*>(g_A8)[t] = o;
}

__global__ void conv_w_kernel(const float4* __restrict__ w) {
    size_t t = (size_t)blockIdx.x * blockDim.x + threadIdx.x;
    uint4 o = make_uint4(0u, 0u, 0u, 0u);
    if (t * 16 < (size_t)C_DIM * K_DIM) {   // rows >= 1000 stay zero
        const float4* p = w + t * 4;
        o.x = pack4(p[0]); o.y = pack4(p[1]);
        o.z = pack4(p[2]); o.w = pack4(p[3]);
    }
    reinterpret_cast<uint4*>(g_W8)[t] = o;
}

// ============================================================================
// Kernel 3: int8 IMMA GEMM, cp.async 3-stage pipeline
//   D[M,N] = A[M,K] (s8) @ B[N,K]^T (s8), s32 accum -> f32 out
// ============================================================================
__global__ void __launch_bounds__(256, 2)
bgemm_kernel(float* __restrict__ out) {
    extern __shared__ char smem[];
    const uint32_t sb = (uint32_t)__cvta_generic_to_shared(smem);

    const int tid = threadIdx.x;
    const int lane = tid & 31;
    const int wid = tid >> 5;
    const int wm = wid & 1;        // 2 warp rows   (64 m each)
    const int wn = wid >> 1;       // 4 warp cols   (32 n each)
    const int m0 = blockIdx.y * BM;
    const int n0 = blockIdx.x * BN;

    const int8_t* gA = g_A8 + (size_t)m0 * K_DIM;
    const int8_t* gW = g_W8 + (size_t)n0 * K_DIM;

    // ---- g2s copy offsets: thread t copies 4x 16B for A and 4x 16B for B ----
    // idx = tid + i*256 in [0,1024): row = idx/8, col16 = (idx%8)*16
    uint32_t a_dst[4], b_dst[4];
    size_t   a_src[4], b_src[4];
#pragma unroll
    for (int i = 0; i < 4; i++) {
        uint32_t idx = tid + i * 256;
        uint32_t row = idx >> 3, col = (idx & 7u) * 16u;
        a_dst[i] = swz(row, col);
        b_dst[i] = swz(row, col);
        a_src[i] = (size_t)row * K_DIM + col;
        b_src[i] = (size_t)row * K_DIM + col;
    }

    // ---- ldmatrix address components (per thread) ----
    // A: 16x32 tile; thread t -> row (t&15), k-half (t>>4)*16
    uint32_t a_rowoff[4], a_xor[4];
    {
        int arl = lane & 15;
        for (int mt = 0; mt < 4; mt++) {
            uint32_t row = wm * 64 + mt * 16 + arl;
            a_rowoff[mt] = row * BK;
            a_xor[mt] = (row & 7u) * 16u;
        }
    }
    const uint32_t a_colh = ((lane >> 4) & 1) * 16;
    // B: pair of 8x32 n-tiles per ldmatrix.x4
    // thread t -> n row = 2p*8 + ((t>>4)&1)*8 + (t&7), k-half ((t>>3)&1)*16
    uint32_t b_rowoff[2], b_xor[2];
    {
        int nb = wn * 32 + ((lane >> 4) & 1) * 8 + (lane & 7);
        for (int p = 0; p < 2; p++) {
            uint32_t nr = nb + p * 16;
            b_rowoff[p] = nr * BK;
            b_xor[p] = (nr & 7u) * 16u;
        }
    }
    const uint32_t b_colh = ((lane >> 3) & 1) * 16;

    int acc[4][4][4];
#pragma unroll
    for (int i = 0; i < 4; i++)
#pragma unroll
        for (int j = 0; j < 4; j++)
#pragma unroll
            for (int r = 0; r < 4; r++) acc[i][j][r] = 0;

    // ---- prologue: stages 0,1 ----
#pragma unroll
    for (int s = 0; s < 2; s++) {
        uint32_t base = sb + s * STG_BYTES;
        const int8_t* ga = gA + s * BK;
        const int8_t* gw = gW + s * BK;
#pragma unroll
        for (int i = 0; i < 4; i++) cp16(base + a_dst[i], ga + a_src[i]);
#pragma unroll
        for (int i = 0; i < 4; i++) cp16(base + A_ST + b_dst[i], gw + b_src[i]);
        cp_commit();
    }

    // ---- main loop ----
    for (int c = 0; c < NCHUNK; c++) {
        int cn = c + 2;
        if (cn < NCHUNK) {
            uint32_t base = sb + (cn % STAGES) * STG_BYTES;
            const int8_t* ga = gA + cn * BK;
            const int8_t* gw = gW + cn * BK;
#pragma unroll
            for (int i = 0; i < 4; i++) cp16(base + a_dst[i], ga + a_src[i]);
#pragma unroll
            for (int i = 0; i < 4; i++) cp16(base + A_ST + b_dst[i], gw + b_src[i]);
        }
        cp_commit();
        cp_wait2();
        __syncthreads();

        uint32_t sa = sb + (c % STAGES) * STG_BYTES;
        uint32_t sB = sa + A_ST;
#pragma unroll
        for (int ks = 0; ks < 4; ks++) {
            const uint32_t kc = ks * 32;
            uint32_t af[4][4];
#pragma unroll
            for (int mt = 0; mt < 4; mt++) {
                uint32_t addr = sa + a_rowoff[mt] + ((kc + a_colh) ^ a_xor[mt]);
                ldsm_x4(af[mt][0], af[mt][1], af[mt][2], af[mt][3], addr);
            }
            uint32_t bf[4][2];
#pragma unroll
            for (int p = 0; p < 2; p++) {
                uint32_t addr = sB + b_rowoff[p] + ((kc + b_colh) ^ b_xor[p]);
                ldsm_x4(bf[2 * p][0], bf[2 * p][1],
                        bf[2 * p + 1][0], bf[2 * p + 1][1], addr);
            }
#pragma unroll
            for (int mt = 0; mt < 4; mt++)
#pragma unroll
                for (int nt = 0; nt < 4; nt++)
                    imma16832(acc[mt][nt], af[mt], bf[nt][0], bf[nt][1]);
        }
        __syncthreads();
    }

    // ---- epilogue: s32 -> f32, guarded stores (cols >= 1000 dropped) ----
    const int rbase = m0 + wm * 64 + (lane >> 2);
    const int cbase = n0 + wn * 32 + (lane & 3) * 2;
#pragma unroll
    for (int mt = 0; mt < 4; mt++) {
#pragma unroll
        for (int nt = 0; nt < 4; nt++) {
            int col = cbase + nt * 8;
            if (col < C_DIM) {
                int row = rbase + mt * 16;
                float2 v0 = make_float2((float)acc[mt][nt][0],
                                        (float)acc[mt][nt][1]);
                float2 v1 = make_float2((float)acc[mt][nt][2],
                                        (float)acc[mt][nt][3]);
                *reinterpret_cast<float2*>(out + (size_t)row * C_DIM + col) = v0;
                *reinterpret_cast<float2*>(out + (size_t)(row + 8) * C_DIM + col) = v1;
            }
        }
    }
}

// ============================================================================
// Host side
// ============================================================================
extern "C" void kernel_launch(void* const* d_in, const int* in_sizes, int n_in,
                              void* d_out, int out_size) {
    const float* inp = (const float*)d_in[0];   // [8192, 12288] fp32
    const float* wgt = (const float*)d_in[1];   // [1000, 12288] fp32
    float* out = (float*)d_out;                 // [8192, 1000] fp32

    // 1) sign-quantize to s8
    {
        unsigned nthr = (unsigned)(((size_t)M_DIM * K_DIM / 16) / 256);  // 24576
        conv_a_kernel<<<nthr, 256>>>((const float4*)inp);
    }
    {
        unsigned nthr = (unsigned)(((size_t)N_PAD * K_DIM / 16) / 256);  // 3072
        conv_w_kernel<<<nthr, 256>>>((const float4*)wgt);
    }

    // 2) int8 IMMA GEMM
    static bool attr_set = false;
    if (!attr_set) {
        cudaFuncSetAttribute(bgemm_kernel,
                             cudaFuncAttributeMaxDynamicSharedMemorySize,
                             SMEM_BYTES);
        attr_set = true;
    }
    dim3 grid(N_PAD / BN, M_DIM / BM);  // (8, 64)
    bgemm_kernel<<<grid, 256, SMEM_BYTES>>>(out);
}

// round 10
// speedup vs baseline: 1.6173x; 1.6173x over previous
#include <cuda_runtime.h>
#include <cstdint>

// ============================================================================
// Problem constants
// ============================================================================
#define K_DIM 12288
#define M_DIM 8192
#define C_DIM 1000
#define N_PAD 1024

// GEMM tiling (int8 TN: A[M,K] row-major, B[N,K] row-major = "col" operand)
#define BM 128
#define BN 128
#define BK 128                      // bytes of K per stage
#define NCHUNK (K_DIM / BK)         // 96
#define STAGES 3
#define A_ST (BM * BK)              // 16384 B
#define B_ST (BN * BK)              // 16384 B
#define STG_BYTES (A_ST + B_ST)     // 32768 B
#define SMEM_BYTES (STAGES * STG_BYTES)  // 98304 B

// conv grid split
#define A_GROUPS ((size_t)M_DIM * K_DIM / 16)   // 6291456 threads
#define W_GROUPS ((size_t)N_PAD * K_DIM / 16)   // 786432 threads
#define A_BLOCKS (A_GROUPS / 256)               // 24576
#define W_BLOCKS (W_GROUPS / 256)               // 3072

// ============================================================================
// Device scratch (allocation-free: __device__ globals)
// ============================================================================
__device__ int8_t g_A8[(size_t)M_DIM * K_DIM];   // sign(input)  as s8
__device__ int8_t g_W8[(size_t)N_PAD * K_DIM];   // sign(weight) as s8, zero-pad

// ============================================================================
// Helpers
// ============================================================================
// SW128-style swizzle: 128B rows, XOR 16B-column index with (row % 8)
__device__ __forceinline__ uint32_t swz(uint32_t row, uint32_t col) {
    return row * BK + (col ^ ((row & 7u) * 16u));
}

__device__ __forceinline__ void cp16(uint32_t dst, const void* src) {
    asm volatile("cp.async.cg.shared.global [%0], [%1], 16;"
                 :: "r"(dst), "l"(src));
}
__device__ __forceinline__ void cp_commit() {
    asm volatile("cp.async.commit_group;");
}
__device__ __forceinline__ void cp_wait2() {
    asm volatile("cp.async.wait_group 2;");
}

__device__ __forceinline__ void ldsm_x4(uint32_t& r0, uint32_t& r1,
                                        uint32_t& r2, uint32_t& r3,
                                        uint32_t addr) {
    asm volatile("ldmatrix.sync.aligned.m8n8.x4.shared.b16 {%0,%1,%2,%3}, [%4];"
                 : "=r"(r0), "=r"(r1), "=r"(r2), "=r"(r3) : "r"(addr));
}

__device__ __forceinline__ void imma16832(int* c, const uint32_t* a,
                                          uint32_t b0, uint32_t b1) {
    asm volatile(
        "mma.sync.aligned.m16n8k32.row.col.s32.s8.s8.s32 "
        "{%0,%1,%2,%3}, {%4,%5,%6,%7}, {%8,%9}, {%0,%1,%2,%3};"
        : "+r"(c[0]), "+r"(c[1]), "+r"(c[2]), "+r"(c[3])
        : "r"(a[0]), "r"(a[1]), "r"(a[2]), "r"(a[3]), "r"(b0), "r"(b1));
}

__device__ __forceinline__ int8_t sgn8(float x) {
    return (int8_t)((x > 0.f) - (x < 0.f));
}
__device__ __forceinline__ uint32_t pack4(float4 f) {
    uint32_t a = (uint8_t)sgn8(f.x), b = (uint8_t)sgn8(f.y);
    uint32_t c = (uint8_t)sgn8(f.z), d = (uint8_t)sgn8(f.w);
    return a | (b << 8) | (c << 16) | (d << 24);
}

// ============================================================================
// Kernel 1: fused sign-quantize fp32 -> s8 for A and W (16 elems/thread)
// One kernel so the per-call launch sequence is [conv, gemm] and ncu -s 5
// lands on the GEMM.
// ============================================================================
__global__ void conv_kernel(const float4* __restrict__ in,
                            const float4* __restrict__ w) {
    size_t b = blockIdx.x;
    if (b < A_BLOCKS) {
        size_t t = b * 256 + threadIdx.x;
        const float4* p = in + t * 4;
        uint4 o;
        o.x = pack4(p[0]); o.y = pack4(p[1]);
        o.z = pack4(p[2]); o.w = pack4(p[3]);
        reinterpret_cast<uint4*>(g_A8)[t] = o;
    } else {
        size_t t = (b - A_BLOCKS) * 256 + threadIdx.x;
        uint4 o = make_uint4(0u, 0u, 0u, 0u);
        if (t * 16 < (size_t)C_DIM * K_DIM) {   // rows >= 1000 stay zero
            const float4* p = w + t * 4;
            o.x = pack4(p[0]); o.y = pack4(p[1]);
            o.z = pack4(p[2]); o.w = pack4(p[3]);
        }
        reinterpret_cast<uint4*>(g_W8)[t] = o;
    }
}

// ============================================================================
// Kernel 2: int8 IMMA GEMM, cp.async 3-stage pipeline
//   D[M,N] = A[M,K] (s8) @ B[N,K]^T (s8), s32 accum -> f32 out
// Register-pressure-reduced: peak live fragments 12 (bf 8 + af 4),
// shared dst/src offset arrays (A and B use identical patterns).
// ============================================================================
__global__ void __launch_bounds__(256, 2)
bgemm_kernel(float* __restrict__ out) {
    extern __shared__ char smem[];
    const uint32_t sb = (uint32_t)__cvta_generic_to_shared(smem);

    const int tid = threadIdx.x;
    const int lane = tid & 31;
    const int wid = tid >> 5;
    const int wm = wid & 1;        // 2 warp rows   (64 m each)
    const int wn = wid >> 1;       // 4 warp cols   (32 n each)
    const int m0 = blockIdx.y * BM;
    const int n0 = blockIdx.x * BN;

    const int8_t* gA = g_A8 + (size_t)m0 * K_DIM;
    const int8_t* gW = g_W8 + (size_t)n0 * K_DIM;

    // ---- g2s copy offsets (identical pattern for A and B tiles) ----
    // idx = tid + i*256 in [0,1024): row = idx/8, col16 = (idx%8)*16
    uint32_t dsto[4], srco[4];
#pragma unroll
    for (int i = 0; i < 4; i++) {
        uint32_t idx = tid + i * 256;
        uint32_t row = idx >> 3, col = (idx & 7u) * 16u;
        dsto[i] = swz(row, col);
        srco[i] = row * K_DIM + col;   // < 2^21, fits u32
    }

    // ---- ldmatrix address components (per thread) ----
    // A: 16x32 tile; lane -> row (lane&15), k-half (lane>>4)*16
    uint32_t a_rowoff[4], a_xor[4];
    {
        int arl = lane & 15;
#pragma unroll
        for (int mt = 0; mt < 4; mt++) {
            uint32_t row = wm * 64 + mt * 16 + arl;
            a_rowoff[mt] = row * BK;
            a_xor[mt] = (row & 7u) * 16u;
        }
    }
    const uint32_t a_colh = ((lane >> 4) & 1) * 16;
    // B: pair of 8x32 n-tiles per ldmatrix.x4
    uint32_t b_rowoff[2], b_xor[2];
    {
        int nb = wn * 32 + ((lane >> 4) & 1) * 8 + (lane & 7);
#pragma unroll
        for (int p = 0; p < 2; p++) {
            uint32_t nr = nb + p * 16;
            b_rowoff[p] = nr * BK;
            b_xor[p] = (nr & 7u) * 16u;
        }
    }
    const uint32_t b_colh = ((lane >> 3) & 1) * 16;

    int acc[4][4][4];
#pragma unroll
    for (int i = 0; i < 4; i++)
#pragma unroll
        for (int j = 0; j < 4; j++)
#pragma unroll
            for (int r = 0; r < 4; r++) acc[i][j][r] = 0;

    // ---- prologue: stages 0,1 ----
#pragma unroll
    for (int s = 0; s < 2; s++) {
        uint32_t base = sb + s * STG_BYTES;
        const int8_t* ga = gA + s * BK;
        const int8_t* gw = gW + s * BK;
#pragma unroll
        for (int i = 0; i < 4; i++) cp16(base + dsto[i], ga + srco[i]);
#pragma unroll
        for (int i = 0; i < 4; i++) cp16(base + A_ST + dsto[i], gw + srco[i]);
        cp_commit();
    }

    // ---- main loop ----
    for (int c = 0; c < NCHUNK; c++) {
        int cn = c + 2;
        if (cn < NCHUNK) {
            uint32_t base = sb + (cn % STAGES) * STG_BYTES;
            const int8_t* ga = gA + cn * BK;
            const int8_t* gw = gW + cn * BK;
#pragma unroll
            for (int i = 0; i < 4; i++) cp16(base + dsto[i], ga + srco[i]);
#pragma unroll
            for (int i = 0; i < 4; i++) cp16(base + A_ST + dsto[i], gw + srco[i]);
        }
        cp_commit();
        cp_wait2();
        __syncthreads();

        uint32_t sa = sb + (c % STAGES) * STG_BYTES;
        uint32_t sB = sa + A_ST;
#pragma unroll
        for (int ks = 0; ks < 4; ks++) {
            const uint32_t kc = ks * 32;
            // B fragments first (8 regs live across the mt loop)
            uint32_t bf[4][2];
#pragma unroll
            for (int p = 0; p < 2; p++) {
                uint32_t addr = sB + b_rowoff[p] + ((kc + b_colh) ^ b_xor[p]);
                ldsm_x4(bf[2 * p][0], bf[2 * p][1],
                        bf[2 * p + 1][0], bf[2 * p + 1][1], addr);
            }
            // A fragments loaded per-mt and consumed immediately (4 regs)
#pragma unroll
            for (int mt = 0; mt < 4; mt++) {
                uint32_t af[4];
                uint32_t addr = sa + a_rowoff[mt] + ((kc + a_colh) ^ a_xor[mt]);
                ldsm_x4(af[0], af[1], af[2], af[3], addr);
#pragma unroll
                for (int nt = 0; nt < 4; nt++)
                    imma16832(acc[mt][nt], af, bf[nt][0], bf[nt][1]);
            }
        }
        __syncthreads();
    }

    // ---- epilogue: s32 -> f32, guarded stores (cols >= 1000 dropped) ----
    const int rbase = m0 + wm * 64 + (lane >> 2);
    const int cbase = n0 + wn * 32 + (lane & 3) * 2;
#pragma unroll
    for (int mt = 0; mt < 4; mt++) {
#pragma unroll
        for (int nt = 0; nt < 4; nt++) {
            int col = cbase + nt * 8;
            if (col < C_DIM) {
                int row = rbase + mt * 16;
                float2 v0 = make_float2((float)acc[mt][nt][0],
                                        (float)acc[mt][nt][1]);
                float2 v1 = make_float2((float)acc[mt][nt][2],
                                        (float)acc[mt][nt][3]);
                *reinterpret_cast<float2*>(out + (size_t)row * C_DIM + col) = v0;
                *reinterpret_cast<float2*>(out + (size_t)(row + 8) * C_DIM + col) = v1;
            }
        }
    }
}

// ============================================================================
// Host side
// ============================================================================
extern "C" void kernel_launch(void* const* d_in, const int* in_sizes, int n_in,
                              void* d_out, int out_size) {
    const float* inp = (const float*)d_in[0];   // [8192, 12288] fp32
    const float* wgt = (const float*)d_in[1];   // [1000, 12288] fp32
    float* out = (float*)d_out;                 // [8192, 1000] fp32

    // 1) fused sign-quantize to s8 (A + W)
    conv_kernel<<<(unsigned)(A_BLOCKS + W_BLOCKS), 256>>>(
        (const float4*)inp, (const float4*)wgt);

    // 2) int8 IMMA GEMM
    static bool attr_set = false;
    if (!attr_set) {
        cudaFuncSetAttribute(bgemm_kernel,
                             cudaFuncAttributeMaxDynamicSharedMemorySize,
                             SMEM_BYTES);
        attr_set = true;
    }
    dim3 grid(N_PAD / BN, M_DIM / BM);  // (8, 64)
    bgemm_kernel<<<grid, 256, SMEM_BYTES>>>(out);
}

// round 11
// speedup vs baseline: 1.8141x; 1.1216x over previous
#include <cuda_runtime.h>
#include <cstdint>

// ============================================================================
// Problem constants
// ============================================================================
#define K_DIM 12288
#define M_DIM 8192
#define C_DIM 1000
#define N_PAD 1024

// GEMM tiling (int8 TN: A[M,K] row-major, B[N,K] row-major = "col" operand)
#define BM 128
#define BN 128
#define BK 128                      // bytes of K per chunk
#define CPT 96                      // chunks per tile (K_DIM / BK)
#define NTILES 512                  // (M/BM) * (N_PAD/BN) = 64*8
#define TOTAL_UNITS (NTILES * CPT)  // 49152 chunk-units
#define NCTA 296                    // 148 SMs * occ 2 -> single balanced wave
#define UNITS_BASE (TOTAL_UNITS / NCTA)          // 166
#define UNITS_REM  (TOTAL_UNITS - NCTA * UNITS_BASE)  // 16

#define STAGES 3
#define A_ST (BM * BK)              // 16384 B
#define B_ST (BN * BK)              // 16384 B
#define STG_BYTES (A_ST + B_ST)     // 32768 B
#define SMEM_BYTES (STAGES * STG_BYTES)  // 98304 B

// conv grid split
#define A_BLOCKS 24576              // (M*K/16)/256
#define W_BLOCKS 3072               // (N_PAD*K/16)/256

// ============================================================================
// Device scratch (allocation-free: __device__ globals)
// ============================================================================
__device__ int8_t g_A8[(size_t)M_DIM * K_DIM];   // sign(input)  as s8
__device__ int8_t g_W8[(size_t)N_PAD * K_DIM];   // sign(weight) as s8, zero-pad

// ============================================================================
// PTX helpers
// ============================================================================
__device__ __forceinline__ void cp16(uint32_t dst, const void* src) {
    asm volatile("cp.async.cg.shared.global [%0], [%1], 16;"
                 :: "r"(dst), "l"(src));
}
__device__ __forceinline__ void cp_commit() {
    asm volatile("cp.async.commit_group;");
}
__device__ __forceinline__ void cp_wait2() {
    asm volatile("cp.async.wait_group 2;");
}

__device__ __forceinline__ void ldsm_x4(uint32_t& r0, uint32_t& r1,
                                        uint32_t& r2, uint32_t& r3,
                                        uint32_t addr) {
    asm volatile("ldmatrix.sync.aligned.m8n8.x4.shared.b16 {%0,%1,%2,%3}, [%4];"
                 : "=r"(r0), "=r"(r1), "=r"(r2), "=r"(r3) : "r"(addr));
}

__device__ __forceinline__ void imma16832(int* c, const uint32_t* a,
                                          uint32_t b0, uint32_t b1) {
    asm volatile(
        "mma.sync.aligned.m16n8k32.row.col.s32.s8.s8.s32 "
        "{%0,%1,%2,%3}, {%4,%5,%6,%7}, {%8,%9}, {%0,%1,%2,%3};"
        : "+r"(c[0]), "+r"(c[1]), "+r"(c[2]), "+r"(c[3])
        : "r"(a[0]), "r"(a[1]), "r"(a[2]), "r"(a[3]), "r"(b0), "r"(b1));
}

__device__ __forceinline__ int8_t sgn8(float x) {
    return (int8_t)((x > 0.f) - (x < 0.f));
}
__device__ __forceinline__ uint32_t pack4(float4 f) {
    uint32_t a = (uint8_t)sgn8(f.x), b = (uint8_t)sgn8(f.y);
    uint32_t c = (uint8_t)sgn8(f.z), d = (uint8_t)sgn8(f.w);
    return a | (b << 8) | (c << 16) | (d << 24);
}

// ============================================================================
// Kernel 1: fused sign-quantize fp32 -> s8 for A and W (16 elems/thread)
// ============================================================================
__global__ void conv_kernel(const float4* __restrict__ in,
                            const float4* __restrict__ w) {
    size_t b = blockIdx.x;
    if (b < A_BLOCKS) {
        size_t t = b * 256 + threadIdx.x;
        const float4* p = in + t * 4;
        uint4 o;
        o.x = pack4(p[0]); o.y = pack4(p[1]);
        o.z = pack4(p[2]); o.w = pack4(p[3]);
        reinterpret_cast<uint4*>(g_A8)[t] = o;
    } else {
        size_t t = (b - A_BLOCKS) * 256 + threadIdx.x;
        uint4 o = make_uint4(0u, 0u, 0u, 0u);
        if (t * 16 < (size_t)C_DIM * K_DIM) {   // rows >= 1000 stay zero
            const float4* p = w + t * 4;
            o.x = pack4(p[0]); o.y = pack4(p[1]);
            o.z = pack4(p[2]); o.w = pack4(p[3]);
        }
        reinterpret_cast<uint4*>(g_W8)[t] = o;
    }
}

// ============================================================================
// Kernel 2: int8 IMMA GEMM, balanced chunk-unit distribution.
// 296 CTAs (one full wave at occ 2) each process a contiguous range of
// chunk-units (tile-id * 96 + k-chunk). Partial-K results are atomicAdd'ed
// into the fp32 output (exact: integer-valued, |v| <= 12288).
// ============================================================================
__global__ void __launch_bounds__(256, 2)
bgemm_kernel(float* __restrict__ out) {
    extern __shared__ char smem[];
    const uint32_t sb = (uint32_t)__cvta_generic_to_shared(smem);

    const int tid = threadIdx.x;
    const int lane = tid & 31;
    const int wid = tid >> 5;
    const int wm = wid & 1;        // 2 warp rows   (64 m each)
    const int wn = wid >> 1;       // 4 warp cols   (32 n each)

    // ---- g2s copy offsets, base forms (i-th copy adds i*4096 / i*32*K_DIM) ----
    const uint32_t row0 = tid >> 3;
    const uint32_t col0 = (tid & 7u) * 16u;
    const uint32_t dst0 = row0 * BK + (col0 ^ ((row0 & 7u) * 16u));
    const uint32_t src0 = row0 * K_DIM + col0;

    // ---- ldmatrix address components ----
    const uint32_t lswz = (lane & 7u) * 16u;
    const uint32_t a_r0off = (uint32_t)(wm * 64 + (lane & 15)) * BK;
    const uint32_t axc = (((lane >> 4) & 1u) * 16u) ^ lswz;
    const uint32_t b_r0off =
        (uint32_t)(wn * 32 + ((lane >> 4) & 1) * 8 + (lane & 7)) * BK;
    const uint32_t bxc = (((lane >> 3) & 1u) * 16u) ^ lswz;

    // ---- balanced work range ----
    const int bid = blockIdx.x;
    int u = bid * UNITS_BASE + min(bid, UNITS_REM);
    const int u_end = u + UNITS_BASE + (bid < UNITS_REM ? 1 : 0);

    int acc[4][4][4];

    while (u < u_end) {
        const int t = u / CPT;
        const int c0 = u - t * CPT;
        const int nch = min(CPT - c0, u_end - u);
        const int tm = t >> 3, tn = t & 7;

        const int8_t* gA = g_A8 + (size_t)(tm * BM) * K_DIM + (size_t)c0 * BK;
        const int8_t* gW = g_W8 + (size_t)(tn * BN) * K_DIM + (size_t)c0 * BK;

#pragma unroll
        for (int i = 0; i < 4; i++)
#pragma unroll
            for (int j = 0; j < 4; j++)
#pragma unroll
                for (int r = 0; r < 4; r++) acc[i][j][r] = 0;

        // ---- prologue: up to 2 stages ----
#pragma unroll
        for (int s = 0; s < 2; s++) {
            if (s < nch) {
                uint32_t base = sb + s * STG_BYTES;
                const int8_t* ga = gA + s * BK;
                const int8_t* gw = gW + s * BK;
#pragma unroll
                for (int i = 0; i < 4; i++)
                    cp16(base + dst0 + i * 4096,
                         ga + src0 + (size_t)i * (32 * K_DIM));
#pragma unroll
                for (int i = 0; i < 4; i++)
                    cp16(base + A_ST + dst0 + i * 4096,
                         gw + src0 + (size_t)i * (32 * K_DIM));
            }
            cp_commit();
        }

        // ---- main loop over this segment's chunks ----
        for (int c = 0; c < nch; c++) {
            int cn = c + 2;
            if (cn < nch) {
                uint32_t base = sb + (cn % STAGES) * STG_BYTES;
                const int8_t* ga = gA + cn * BK;
                const int8_t* gw = gW + cn * BK;
#pragma unroll
                for (int i = 0; i < 4; i++)
                    cp16(base + dst0 + i * 4096,
                         ga + src0 + (size_t)i * (32 * K_DIM));
#pragma unroll
                for (int i = 0; i < 4; i++)
                    cp16(base + A_ST + dst0 + i * 4096,
                         gw + src0 + (size_t)i * (32 * K_DIM));
            }
            cp_commit();
            cp_wait2();
            __syncthreads();

            uint32_t sa = sb + (c % STAGES) * STG_BYTES;
            uint32_t sB = sa + A_ST;
#pragma unroll
            for (int ks = 0; ks < 4; ks++) {
                const uint32_t kc = ks * 32;
                // B fragments (8 regs live across the mt loop)
                uint32_t bf[4][2];
#pragma unroll
                for (int p = 0; p < 2; p++) {
                    uint32_t addr = sB + b_r0off + p * 2048 + (kc ^ bxc);
                    ldsm_x4(bf[2 * p][0], bf[2 * p][1],
                            bf[2 * p + 1][0], bf[2 * p + 1][1], addr);
                }
                // A fragments loaded per-mt, consumed immediately
#pragma unroll
                for (int mt = 0; mt < 4; mt++) {
                    uint32_t af[4];
                    uint32_t addr = sa + a_r0off + mt * 2048 + (kc ^ axc);
                    ldsm_x4(af[0], af[1], af[2], af[3], addr);
#pragma unroll
                    for (int nt = 0; nt < 4; nt++)
                        imma16832(acc[mt][nt], af, bf[nt][0], bf[nt][1]);
                }
            }
            __syncthreads();
        }

        // ---- segment epilogue: atomic accumulate (exact fp32 integer adds) ----
        {
            const int rbase = tm * BM + wm * 64 + (lane >> 2);
            const int cbase = tn * BN + wn * 32 + (lane & 3) * 2;
#pragma unroll
            for (int mt = 0; mt < 4; mt++) {
#pragma unroll
                for (int nt = 0; nt < 4; nt++) {
                    int col = cbase + nt * 8;
                    if (col < C_DIM) {
                        int row = rbase + mt * 16;
                        float* o0 = out + (size_t)row * C_DIM + col;
                        atomicAdd(o0,     (float)acc[mt][nt][0]);
                        atomicAdd(o0 + 1, (float)acc[mt][nt][1]);
                        float* o1 = out + (size_t)(row + 8) * C_DIM + col;
                        atomicAdd(o1,     (float)acc[mt][nt][2]);
                        atomicAdd(o1 + 1, (float)acc[mt][nt][3]);
                    }
                }
            }
        }

        u += nch;
    }
}

// ============================================================================
// Host side
// ============================================================================
extern "C" void kernel_launch(void* const* d_in, const int* in_sizes, int n_in,
                              void* d_out, int out_size) {
    const float* inp = (const float*)d_in[0];   // [8192, 12288] fp32
    const float* wgt = (const float*)d_in[1];   // [1000, 12288] fp32
    float* out = (float*)d_out;                 // [8192, 1000] fp32

    // 1) fused sign-quantize to s8 (A + W)
    conv_kernel<<<(unsigned)(A_BLOCKS + W_BLOCKS), 256>>>(
        (const float4*)inp, (const float4*)wgt);

    // 2) zero output (atomic accumulation target; graph replays re-zero)
    cudaMemsetAsync(out, 0, (size_t)out_size * sizeof(float));

    // 3) int8 IMMA GEMM, balanced single-wave distribution
    static bool attr_set = false;
    if (!attr_set) {
        cudaFuncSetAttribute(bgemm_kernel,
                             cudaFuncAttributeMaxDynamicSharedMemorySize,
                             SMEM_BYTES);
        attr_set = true;
    }
    bgemm_kernel<<<NCTA, 256, SMEM_BYTES>>>(out);
}